// round 13
// baseline (speedup 1.0000x reference)
#include <cuda_runtime.h>
#include <cuda_fp16.h>
#include <cuda_bf16.h>
#include <cstdint>

#define NN 100000
#define EE 1000000
#define HH 64
#define GG 64
#define CC 3
#define FIN1 32
#define BK 48                     // bucket capacity per node (P(deg>48) ~ 1e-16)

// ---------------- scratch ----------------
__device__ __align__(16) __half g_hp[NN * HH];     // h' = (in@W)*dinv, fp16 rows (128B)
__device__ __align__(16) __half g_buf2h[NN * HH];  // y (layers 1,2), fp16
__device__ float g_cnt[GG];
__device__ __align__(16) float g_pooled[GG * HH];
__device__ float g_sum[3 * HH];
__device__ float g_sq[3 * HH];
// fp16 weights (preconverted once per call)
__device__ __align__(16) __half g_w1h[FIN1 * HH];
__device__ __align__(16) __half g_w2h[HH * HH];
__device__ __align__(16) __half g_w3h[HH * HH];
// bucketed CSR
__device__ int g_deg[NN];                          // zeroed by gather<2> each call
__device__ __align__(16) int g_col[NN * BK + 8];

__device__ __forceinline__ uint32_t smem_u32(const void* p) {
    return (uint32_t)__cvta_generic_to_shared(p);
}
__device__ __forceinline__ uint32_t h2u(__half2 h) {
    return *reinterpret_cast<uint32_t*>(&h);
}

// ---------------- prep: convert W1/W2/W3 to fp16 ----------------
__global__ void prep_kernel(const float* __restrict__ W1, const float* __restrict__ W2,
                            const float* __restrict__ W3) {
    int t = blockIdx.x * 256 + threadIdx.x;
    if (t < FIN1 * HH) g_w1h[t] = __float2half(W1[t]);
    if (t < HH * HH) {
        g_w2h[t] = __float2half(W2[t]);
        g_w3h[t] = __float2half(W3[t]);
    }
}

// ---------------- bucket fill: deg count + col scatter in ONE pass ----------------
__global__ void fill_kernel(const int* __restrict__ ei) {
    int e4 = blockIdx.x * blockDim.x + threadIdx.x;
    if (e4 < EE / 4) {
        int4 s = __ldg(reinterpret_cast<const int4*>(ei) + e4);
        int4 d = __ldg(reinterpret_cast<const int4*>(ei + EE) + e4);
        int p;
        p = atomicAdd(&g_deg[d.x], 1); if (p < BK) g_col[d.x * BK + p] = s.x;
        p = atomicAdd(&g_deg[d.y], 1); if (p < BK) g_col[d.y * BK + p] = s.y;
        p = atomicAdd(&g_deg[d.z], 1); if (p < BK) g_col[d.z * BK + p] = s.z;
        p = atomicAdd(&g_deg[d.w], 1); if (p < BK) g_col[d.w * BK + p] = s.w;
    }
}

// ---------------- GEMM via tensor cores: direct-to-fragment A loads ----------------
// 64-node tile; 8 warps: warp w -> rows (w&3)*16.., cols (w>>2)*32..
template <int FIN, int LAYER>
__global__ void __launch_bounds__(256) gemm_kernel(const float* __restrict__ xin,
                                                   const __half* __restrict__ Wh,
                                                   const float* __restrict__ gm,
                                                   const float* __restrict__ be) {
    constexpr int BS = HH + 8;
    __shared__ __half ws[FIN * BS];
    __shared__ float s_scale[64], s_shift[64];

    const int tid = threadIdx.x;
    const int nbase = blockIdx.x * 64;

    if (LAYER > 0 && tid < 64) {
        float invN = 1.0f / (float)NN;
        float m = g_sum[(LAYER - 1) * HH + tid] * invN;
        float v = g_sq[(LAYER - 1) * HH + tid] * invN - m * m;
        float sc = gm[tid] * rsqrtf(v + 1e-5f);
        s_scale[tid] = sc;
        s_shift[tid] = be[tid] - m * sc;
    }
    {   // W staging: fp16, vectorized half2
        const __half2* wsrc = reinterpret_cast<const __half2*>(Wh);
        for (int i = tid; i < FIN * HH / 2; i += 256) {
            int row = i >> 5, col = (i & 31) * 2;
            *reinterpret_cast<__half2*>(&ws[row * BS + col]) = wsrc[i];
        }
    }
    __syncthreads();

    const int w = tid >> 5, lane = tid & 31;
    const int mw = (w & 3) * 16;
    const int nb = (w >> 2) * 32;
    const int cq = (lane & 3) * 2;
    const int row0 = nbase + mw + (lane >> 2);
    const int row1 = row0 + 8;
    const bool ok0 = row0 < NN, ok1 = row1 < NN;

    float acc[4][4] = {{0,0,0,0},{0,0,0,0},{0,0,0,0},{0,0,0,0}};
    const uint32_t ws_base = smem_u32(ws);

#pragma unroll
    for (int k0 = 0; k0 < FIN; k0 += 16) {
        uint32_t a0, a1, a2, a3;
        const int cA = k0 + cq, cB = k0 + cq + 8;
        if (LAYER == 0) {
            float2 z = make_float2(0.f, 0.f);
            float2 f00 = ok0 ? __ldg(reinterpret_cast<const float2*>(&xin[(size_t)row0 * FIN + cA])) : z;
            float2 f10 = ok1 ? __ldg(reinterpret_cast<const float2*>(&xin[(size_t)row1 * FIN + cA])) : z;
            float2 f01 = ok0 ? __ldg(reinterpret_cast<const float2*>(&xin[(size_t)row0 * FIN + cB])) : z;
            float2 f11 = ok1 ? __ldg(reinterpret_cast<const float2*>(&xin[(size_t)row1 * FIN + cB])) : z;
            a0 = h2u(__floats2half2_rn(f00.x, f00.y));
            a1 = h2u(__floats2half2_rn(f10.x, f10.y));
            a2 = h2u(__floats2half2_rn(f01.x, f01.y));
            a3 = h2u(__floats2half2_rn(f11.x, f11.y));
        } else {
            __half2 hz = __floats2half2_rn(0.f, 0.f);
            __half2 h00 = ok0 ? __ldg(reinterpret_cast<const __half2*>(&g_buf2h[(size_t)row0 * 64 + cA])) : hz;
            __half2 h10 = ok1 ? __ldg(reinterpret_cast<const __half2*>(&g_buf2h[(size_t)row1 * 64 + cA])) : hz;
            __half2 h01 = ok0 ? __ldg(reinterpret_cast<const __half2*>(&g_buf2h[(size_t)row0 * 64 + cB])) : hz;
            __half2 h11 = ok1 ? __ldg(reinterpret_cast<const __half2*>(&g_buf2h[(size_t)row1 * 64 + cB])) : hz;
            float sA0 = s_scale[cA], sA1 = s_scale[cA + 1];
            float tA0 = s_shift[cA], tA1 = s_shift[cA + 1];
            float sB0 = s_scale[cB], sB1 = s_scale[cB + 1];
            float tB0 = s_shift[cB], tB1 = s_shift[cB + 1];
            float2 f;
            f = __half22float2(h00);
            a0 = h2u(__floats2half2_rn(fmaxf(fmaf(f.x, sA0, tA0), 0.f), fmaxf(fmaf(f.y, sA1, tA1), 0.f)));
            f = __half22float2(h10);
            a1 = h2u(__floats2half2_rn(fmaxf(fmaf(f.x, sA0, tA0), 0.f), fmaxf(fmaf(f.y, sA1, tA1), 0.f)));
            f = __half22float2(h01);
            a2 = h2u(__floats2half2_rn(fmaxf(fmaf(f.x, sB0, tB0), 0.f), fmaxf(fmaf(f.y, sB1, tB1), 0.f)));
            f = __half22float2(h11);
            a3 = h2u(__floats2half2_rn(fmaxf(fmaf(f.x, sB0, tB0), 0.f), fmaxf(fmaf(f.y, sB1, tB1), 0.f)));
        }
#pragma unroll
        for (int hn = 0; hn < 2; hn++) {
            uint32_t b0, b1, b2, b3;
            uint32_t b_addr = ws_base + ((k0 + (lane & 15)) * BS + nb + hn * 16 + ((lane >> 4) * 8)) * 2;
            asm volatile("ldmatrix.sync.aligned.m8n8.x4.trans.shared.b16 {%0,%1,%2,%3}, [%4];"
                         : "=r"(b0), "=r"(b1), "=r"(b2), "=r"(b3) : "r"(b_addr));
            asm volatile("mma.sync.aligned.m16n8k16.row.col.f32.f16.f16.f32 "
                         "{%0,%1,%2,%3}, {%4,%5,%6,%7}, {%8,%9}, {%0,%1,%2,%3};"
                         : "+f"(acc[hn * 2][0]), "+f"(acc[hn * 2][1]),
                           "+f"(acc[hn * 2][2]), "+f"(acc[hn * 2][3])
                         : "r"(a0), "r"(a1), "r"(a2), "r"(a3), "r"(b0), "r"(b1));
            asm volatile("mma.sync.aligned.m16n8k16.row.col.f32.f16.f16.f32 "
                         "{%0,%1,%2,%3}, {%4,%5,%6,%7}, {%8,%9}, {%0,%1,%2,%3};"
                         : "+f"(acc[hn * 2 + 1][0]), "+f"(acc[hn * 2 + 1][1]),
                           "+f"(acc[hn * 2 + 1][2]), "+f"(acc[hn * 2 + 1][3])
                         : "r"(a0), "r"(a1), "r"(a2), "r"(a3), "r"(b2), "r"(b3));
        }
    }

    const float dv0 = ok0 ? rsqrtf(1.0f + (float)__ldg(&g_deg[row0])) : 0.f;
    const float dv1 = ok1 ? rsqrtf(1.0f + (float)__ldg(&g_deg[row1])) : 0.f;
#pragma unroll
    for (int nt = 0; nt < 4; nt++) {
        int c = nb + nt * 8 + cq;
        if (ok0)
            *reinterpret_cast<__half2*>(&g_hp[(size_t)row0 * 64 + c]) =
                __floats2half2_rn(acc[nt][0] * dv0, acc[nt][1] * dv0);
        if (ok1)
            *reinterpret_cast<__half2*>(&g_hp[(size_t)row1 * 64 + c]) =
                __floats2half2_rn(acc[nt][2] * dv1, acc[nt][3] * dv1);
    }
}

// ---------------- fp16 row accumulate helpers ----------------
__device__ __forceinline__ void add8(float* acc, float4 v) {
    const __half2* h = reinterpret_cast<const __half2*>(&v);
#pragma unroll
    for (int k = 0; k < 4; k++) {
        float2 f = __half22float2(h[k]);
        acc[2 * k]     += f.x;
        acc[2 * k + 1] += f.y;
    }
}
// pairwise: one fp16 add per element pair, then convert+add (halves cvt/FADD count)
__device__ __forceinline__ void add8_pair(float* acc, float4 v0, float4 v1) {
    const __half2* h0 = reinterpret_cast<const __half2*>(&v0);
    const __half2* h1 = reinterpret_cast<const __half2*>(&v1);
#pragma unroll
    for (int k = 0; k < 4; k++) {
        float2 f = __half22float2(__hadd2(h0[k], h1[k]));
        acc[2 * k]     += f.x;
        acc[2 * k + 1] += f.y;
    }
}

// ---------------- bucket gather: 8 threads/node, flat 16-window, paired fp16 adds ----------------
template <int LAYER>
__global__ void __launch_bounds__(256) gather_kernel(const float* __restrict__ b,
                                                     const int* __restrict__ batch) {
    const int tid = threadIdx.x;
    const int q = tid & 7;
    const int nbase = blockIdx.x * 32;
    const int n = nbase + (tid >> 3);             // NN/32 = 3125 exact
    const int c0 = q * 8;

    // per-graph node counts, only needed once (layer 2): warp 0 covers block's 32 nodes
    if (LAYER == 2 && tid < 32) {
        int gr2 = __ldg(&batch[nbase + tid]);
        unsigned mask = __match_any_sync(0xffffffffu, gr2);
        if (tid == __ffs(mask) - 1) atomicAdd(&g_cnt[gr2], (float)__popc(mask));
    }

    float acc[8];
    {   // self term
        float4 v = __ldg(reinterpret_cast<const float4*>(&g_hp[(size_t)n * 64 + c0]));
        const __half2* h = reinterpret_cast<const __half2*>(&v);
#pragma unroll
        for (int k = 0; k < 4; k++) {
            float2 f = __half22float2(h[k]);
            acc[2 * k] = f.x; acc[2 * k + 1] = f.y;
        }
    }

    const int dgr = g_deg[n];                     // broadcast (8 lanes same addr)
    const float dv = rsqrtf(1.0f + (float)dgr);
    const int d = dgr > BK ? BK : dgr;
    const int base = n * BK;

    // flat 16-edge window: indices unconditional, rows predicated, adds paired in fp16
    int idx[16];
#pragma unroll
    for (int k = 0; k < 16; k++) idx[k] = __ldg(&g_col[base + k]);
    const float4 z4 = make_float4(0.f, 0.f, 0.f, 0.f);
#pragma unroll
    for (int k = 0; k < 8; k++) {
        float4 v0 = z4, v1 = z4;
        if (2 * k < d)
            v0 = __ldg(reinterpret_cast<const float4*>(&g_hp[(size_t)idx[2 * k] * 64 + c0]));
        if (2 * k + 1 < d)
            v1 = __ldg(reinterpret_cast<const float4*>(&g_hp[(size_t)idx[2 * k + 1] * 64 + c0]));
        add8_pair(acc, v0, v1);
    }
    // rare remainder (deg > 16, ~2% of nodes)
    for (int i = 16; i < d; i += 4) {
        int s[4];
#pragma unroll
        for (int k = 0; k < 4; k++) s[k] = __ldg(&g_col[base + i + k]);
#pragma unroll
        for (int k = 0; k < 4; k += 2) {
            float4 v0 = z4, v1 = z4;
            if (i + k < d)
                v0 = __ldg(reinterpret_cast<const float4*>(&g_hp[(size_t)s[k] * 64 + c0]));
            if (i + k + 1 < d)
                v1 = __ldg(reinterpret_cast<const float4*>(&g_hp[(size_t)s[k + 1] * 64 + c0]));
            add8_pair(acc, v0, v1);
        }
    }

    float4 bv0 = *reinterpret_cast<const float4*>(&b[c0]);
    float4 bv1 = *reinterpret_cast<const float4*>(&b[c0 + 4]);
    float y[8];
    y[0] = fmaf(acc[0], dv, bv0.x); y[1] = fmaf(acc[1], dv, bv0.y);
    y[2] = fmaf(acc[2], dv, bv0.z); y[3] = fmaf(acc[3], dv, bv0.w);
    y[4] = fmaf(acc[4], dv, bv1.x); y[5] = fmaf(acc[5], dv, bv1.y);
    y[6] = fmaf(acc[6], dv, bv1.z); y[7] = fmaf(acc[7], dv, bv1.w);

    if (LAYER < 2) {
        union { uint4 u; __half2 h[4]; } pk;
#pragma unroll
        for (int k = 0; k < 4; k++) pk.h[k] = __floats2half2_rn(y[2 * k], y[2 * k + 1]);
        *reinterpret_cast<uint4*>(&g_buf2h[(size_t)n * 64 + c0]) = pk.u;
    } else {
        // fused mean-pool accumulation (BN3 applied in head); zero deg for next call
        int gr = __ldg(&batch[n]);
        float* p = &g_pooled[(size_t)gr * 64 + c0];
        asm volatile("red.global.add.v4.f32 [%0], {%1,%2,%3,%4};"
                     :: "l"(p), "f"(y[0]), "f"(y[1]), "f"(y[2]), "f"(y[3]) : "memory");
        asm volatile("red.global.add.v4.f32 [%0], {%1,%2,%3,%4};"
                     :: "l"(p + 4), "f"(y[4]), "f"(y[5]), "f"(y[6]), "f"(y[7]) : "memory");
        if (q == 0) g_deg[n] = 0;      // warp-synchronous: all lanes already read deg
    }

    float s[8], s2[8];
#pragma unroll
    for (int k = 0; k < 8; k++) { s[k] = y[k]; s2[k] = y[k] * y[k]; }
#pragma unroll
    for (int k = 0; k < 8; k++) {
        s[k]  += __shfl_xor_sync(0xffffffffu, s[k], 8);
        s2[k] += __shfl_xor_sync(0xffffffffu, s2[k], 8);
        s[k]  += __shfl_xor_sync(0xffffffffu, s[k], 16);
        s2[k] += __shfl_xor_sync(0xffffffffu, s2[k], 16);
    }
    __shared__ float ss[8][64];
    __shared__ float sg[8][64];
    int w = tid >> 5, lane = tid & 31;
    if (lane < 8) {
        *reinterpret_cast<float4*>(&ss[w][c0])     = make_float4(s[0], s[1], s[2], s[3]);
        *reinterpret_cast<float4*>(&ss[w][c0 + 4]) = make_float4(s[4], s[5], s[6], s[7]);
        *reinterpret_cast<float4*>(&sg[w][c0])     = make_float4(s2[0], s2[1], s2[2], s2[3]);
        *reinterpret_cast<float4*>(&sg[w][c0 + 4]) = make_float4(s2[4], s2[5], s2[6], s2[7]);
    }
    __syncthreads();
    if (tid < 64) {
        float a = 0.f, a2 = 0.f;
#pragma unroll
        for (int ww = 0; ww < 8; ww++) { a += ss[ww][tid]; a2 += sg[ww][tid]; }
        atomicAdd(&g_sum[LAYER * HH + tid], a);
        atomicAdd(&g_sq[LAYER * HH + tid], a2);
    }
}

// ---------------- head: BN3 on pooled means, MLP, softmax; zero globals for next call ----------------
__global__ void head_kernel(const float* __restrict__ gm, const float* __restrict__ be,
                            const float* __restrict__ Wl1, const float* __restrict__ bl1,
                            const float* __restrict__ Wl2, const float* __restrict__ bl2,
                            float* __restrict__ out) {
    __shared__ float ps[GG][64];
    __shared__ float zs[GG][33];
    __shared__ float lg[GG][3];
    __shared__ float s_scale[64], s_shift[64];
    int tid = threadIdx.x;   // 256

    if (tid < 64) {
        float invN = 1.0f / (float)NN;
        float m = g_sum[2 * HH + tid] * invN;
        float v = g_sq[2 * HH + tid] * invN - m * m;
        float sc = gm[tid] * rsqrtf(v + 1e-5f);
        s_scale[tid] = sc;
        s_shift[tid] = be[tid] - m * sc;
    }
    __syncthreads();

    for (int i = tid; i < GG * 64; i += 256) {
        int g = i >> 6, c = i & 63;
        float mean = g_pooled[i] / fmaxf(g_cnt[g], 1.0f);
        ps[g][c] = fmaf(mean, s_scale[c], s_shift[c]);
    }
    __syncthreads();

    // zero accumulators for the next call (all dead now)
    for (int i = tid; i < GG * HH; i += 256) g_pooled[i] = 0.0f;
    if (tid < 3 * HH) { g_sum[tid] = 0.0f; g_sq[tid] = 0.0f; }
    if (tid < GG) g_cnt[tid] = 0.0f;

    for (int i = tid; i < GG * 32; i += 256) {
        int g = i >> 5, j = i & 31;
        float acc = bl1[j];
#pragma unroll
        for (int k = 0; k < 64; k++) acc += ps[g][k] * Wl1[k * 32 + j];
        zs[g][j] = fmaxf(acc, 0.0f);
    }
    __syncthreads();
    if (tid < GG * CC) {
        int g = tid / CC, c = tid % CC;
        float acc = bl2[c];
#pragma unroll
        for (int k = 0; k < 32; k++) acc += zs[g][k] * Wl2[k * CC + c];
        lg[g][c] = acc;
    }
    __syncthreads();
    if (tid < GG) {
        float a = lg[tid][0], b = lg[tid][1], c = lg[tid][2];
        float mx = fmaxf(a, fmaxf(b, c));
        float e0 = expf(a - mx), e1 = expf(b - mx), e2 = expf(c - mx);
        float inv = 1.0f / (e0 + e1 + e2);
        out[tid * 3 + 0] = e0 * inv;
        out[tid * 3 + 1] = e1 * inv;
        out[tid * 3 + 2] = e2 * inv;
    }
}

// ---------------- launch ----------------
extern "C" void kernel_launch(void* const* d_in, const int* in_sizes, int n_in,
                              void* d_out, int out_size) {
    const float* x     = (const float*)d_in[0];
    const int*   ei    = (const int*)d_in[1];
    const int*   batch = (const int*)d_in[2];
    const float* W1  = (const float*)d_in[3];
    const float* b1  = (const float*)d_in[4];
    const float* g1  = (const float*)d_in[5];
    const float* be1 = (const float*)d_in[6];
    const float* W2  = (const float*)d_in[7];
    const float* b2  = (const float*)d_in[8];
    const float* g2  = (const float*)d_in[9];
    const float* be2 = (const float*)d_in[10];
    const float* W3  = (const float*)d_in[11];
    const float* b3  = (const float*)d_in[12];
    const float* g3  = (const float*)d_in[13];
    const float* be3 = (const float*)d_in[14];
    const float* Wl1 = (const float*)d_in[15];
    const float* bl1 = (const float*)d_in[16];
    const float* Wl2 = (const float*)d_in[17];
    const float* bl2 = (const float*)d_in[18];
    float* out = (float*)d_out;

    const int GEMM_GRID   = (NN + 63) / 64;           // 1563
    const int GATHER_GRID = NN / 32;                  // 3125
    const int E4_GRID     = (EE / 4 + 255) / 256;     // 977

    __half* w1h; cudaGetSymbolAddress((void**)&w1h, g_w1h);
    __half* w2h; cudaGetSymbolAddress((void**)&w2h, g_w2h);
    __half* w3h; cudaGetSymbolAddress((void**)&w3h, g_w3h);

    prep_kernel<<<16, 256>>>(W1, W2, W3);
    fill_kernel<<<E4_GRID, 256>>>(ei);

    // ---- layer 1 ----
    gemm_kernel<FIN1, 0><<<GEMM_GRID, 256>>>(x, w1h, nullptr, nullptr);
    gather_kernel<0><<<GATHER_GRID, 256>>>(b1, batch);

    // ---- layer 2 ----
    gemm_kernel<HH, 1><<<GEMM_GRID, 256>>>(nullptr, w2h, g1, be1);
    gather_kernel<1><<<GATHER_GRID, 256>>>(b2, batch);

    // ---- layer 3 (gather pools directly) ----
    gemm_kernel<HH, 2><<<GEMM_GRID, 256>>>(nullptr, w3h, g2, be2);
    gather_kernel<2><<<GATHER_GRID, 256>>>(b3, batch);

    // ---- head ----
    head_kernel<<<1, 256>>>(g3, be3, Wl1, bl1, Wl2, bl2, out);
}

// round 14
// speedup vs baseline: 1.0268x; 1.0268x over previous
#include <cuda_runtime.h>
#include <cuda_fp16.h>
#include <cuda_bf16.h>
#include <cstdint>

#define NN 100000
#define EE 1000000
#define HH 64
#define GG 64
#define CC 3
#define FIN1 32
#define BK 48                     // bucket capacity per node (P(deg>48) ~ 1e-16)

// ---------------- scratch ----------------
__device__ __align__(16) __half g_hp[NN * HH];     // h' = (in@W)*dinv, fp16 rows (128B)
__device__ __align__(16) __half g_buf2h[NN * HH];  // y (layers 1,2), fp16
__device__ float g_cnt[GG];
__device__ __align__(16) float g_pooled[GG * HH];
__device__ float g_sum[3 * HH];
__device__ float g_sq[3 * HH];
// fp16 weights (preconverted once per call)
__device__ __align__(16) __half g_w1h[FIN1 * HH];
__device__ __align__(16) __half g_w2h[HH * HH];
__device__ __align__(16) __half g_w3h[HH * HH];
// bucketed CSR
__device__ int g_deg[NN];                          // zeroed by gather<2> each call
__device__ __align__(16) int g_col[NN * BK + 8];

__device__ __forceinline__ uint32_t smem_u32(const void* p) {
    return (uint32_t)__cvta_generic_to_shared(p);
}
__device__ __forceinline__ uint32_t h2u(__half2 h) {
    return *reinterpret_cast<uint32_t*>(&h);
}

// ---------------- prep: convert W1/W2/W3 to fp16 ----------------
__global__ void prep_kernel(const float* __restrict__ W1, const float* __restrict__ W2,
                            const float* __restrict__ W3) {
    int t = blockIdx.x * 256 + threadIdx.x;
    if (t < FIN1 * HH) g_w1h[t] = __float2half(W1[t]);
    if (t < HH * HH) {
        g_w2h[t] = __float2half(W2[t]);
        g_w3h[t] = __float2half(W3[t]);
    }
}

// ---------------- bucket fill: deg count + col scatter in ONE pass ----------------
__global__ void fill_kernel(const int* __restrict__ ei) {
    int e4 = blockIdx.x * blockDim.x + threadIdx.x;
    if (e4 < EE / 4) {
        int4 s = __ldg(reinterpret_cast<const int4*>(ei) + e4);
        int4 d = __ldg(reinterpret_cast<const int4*>(ei + EE) + e4);
        int p;
        p = atomicAdd(&g_deg[d.x], 1); if (p < BK) g_col[d.x * BK + p] = s.x;
        p = atomicAdd(&g_deg[d.y], 1); if (p < BK) g_col[d.y * BK + p] = s.y;
        p = atomicAdd(&g_deg[d.z], 1); if (p < BK) g_col[d.z * BK + p] = s.z;
        p = atomicAdd(&g_deg[d.w], 1); if (p < BK) g_col[d.w * BK + p] = s.w;
    }
}

// ---------------- GEMM via tensor cores: direct-to-fragment A loads ----------------
// 64-node tile; 8 warps: warp w -> rows (w&3)*16.., cols (w>>2)*32..
template <int FIN, int LAYER>
__global__ void __launch_bounds__(256) gemm_kernel(const float* __restrict__ xin,
                                                   const __half* __restrict__ Wh,
                                                   const float* __restrict__ gm,
                                                   const float* __restrict__ be) {
    constexpr int BS = HH + 8;
    __shared__ __half ws[FIN * BS];
    __shared__ float s_scale[64], s_shift[64];

    const int tid = threadIdx.x;
    const int nbase = blockIdx.x * 64;

    if (LAYER > 0 && tid < 64) {
        float invN = 1.0f / (float)NN;
        float m = g_sum[(LAYER - 1) * HH + tid] * invN;
        float v = g_sq[(LAYER - 1) * HH + tid] * invN - m * m;
        float sc = gm[tid] * rsqrtf(v + 1e-5f);
        s_scale[tid] = sc;
        s_shift[tid] = be[tid] - m * sc;
    }
    {   // W staging: fp16, vectorized half2
        const __half2* wsrc = reinterpret_cast<const __half2*>(Wh);
        for (int i = tid; i < FIN * HH / 2; i += 256) {
            int row = i >> 5, col = (i & 31) * 2;
            *reinterpret_cast<__half2*>(&ws[row * BS + col]) = wsrc[i];
        }
    }
    __syncthreads();

    const int w = tid >> 5, lane = tid & 31;
    const int mw = (w & 3) * 16;
    const int nb = (w >> 2) * 32;
    const int cq = (lane & 3) * 2;
    const int row0 = nbase + mw + (lane >> 2);
    const int row1 = row0 + 8;
    const bool ok0 = row0 < NN, ok1 = row1 < NN;

    float acc[4][4] = {{0,0,0,0},{0,0,0,0},{0,0,0,0},{0,0,0,0}};
    const uint32_t ws_base = smem_u32(ws);

#pragma unroll
    for (int k0 = 0; k0 < FIN; k0 += 16) {
        uint32_t a0, a1, a2, a3;
        const int cA = k0 + cq, cB = k0 + cq + 8;
        if (LAYER == 0) {
            float2 z = make_float2(0.f, 0.f);
            float2 f00 = ok0 ? __ldg(reinterpret_cast<const float2*>(&xin[(size_t)row0 * FIN + cA])) : z;
            float2 f10 = ok1 ? __ldg(reinterpret_cast<const float2*>(&xin[(size_t)row1 * FIN + cA])) : z;
            float2 f01 = ok0 ? __ldg(reinterpret_cast<const float2*>(&xin[(size_t)row0 * FIN + cB])) : z;
            float2 f11 = ok1 ? __ldg(reinterpret_cast<const float2*>(&xin[(size_t)row1 * FIN + cB])) : z;
            a0 = h2u(__floats2half2_rn(f00.x, f00.y));
            a1 = h2u(__floats2half2_rn(f10.x, f10.y));
            a2 = h2u(__floats2half2_rn(f01.x, f01.y));
            a3 = h2u(__floats2half2_rn(f11.x, f11.y));
        } else {
            __half2 hz = __floats2half2_rn(0.f, 0.f);
            __half2 h00 = ok0 ? __ldg(reinterpret_cast<const __half2*>(&g_buf2h[(size_t)row0 * 64 + cA])) : hz;
            __half2 h10 = ok1 ? __ldg(reinterpret_cast<const __half2*>(&g_buf2h[(size_t)row1 * 64 + cA])) : hz;
            __half2 h01 = ok0 ? __ldg(reinterpret_cast<const __half2*>(&g_buf2h[(size_t)row0 * 64 + cB])) : hz;
            __half2 h11 = ok1 ? __ldg(reinterpret_cast<const __half2*>(&g_buf2h[(size_t)row1 * 64 + cB])) : hz;
            float sA0 = s_scale[cA], sA1 = s_scale[cA + 1];
            float tA0 = s_shift[cA], tA1 = s_shift[cA + 1];
            float sB0 = s_scale[cB], sB1 = s_scale[cB + 1];
            float tB0 = s_shift[cB], tB1 = s_shift[cB + 1];
            float2 f;
            f = __half22float2(h00);
            a0 = h2u(__floats2half2_rn(fmaxf(fmaf(f.x, sA0, tA0), 0.f), fmaxf(fmaf(f.y, sA1, tA1), 0.f)));
            f = __half22float2(h10);
            a1 = h2u(__floats2half2_rn(fmaxf(fmaf(f.x, sA0, tA0), 0.f), fmaxf(fmaf(f.y, sA1, tA1), 0.f)));
            f = __half22float2(h01);
            a2 = h2u(__floats2half2_rn(fmaxf(fmaf(f.x, sB0, tB0), 0.f), fmaxf(fmaf(f.y, sB1, tB1), 0.f)));
            f = __half22float2(h11);
            a3 = h2u(__floats2half2_rn(fmaxf(fmaf(f.x, sB0, tB0), 0.f), fmaxf(fmaf(f.y, sB1, tB1), 0.f)));
        }
#pragma unroll
        for (int hn = 0; hn < 2; hn++) {
            uint32_t b0, b1, b2, b3;
            uint32_t b_addr = ws_base + ((k0 + (lane & 15)) * BS + nb + hn * 16 + ((lane >> 4) * 8)) * 2;
            asm volatile("ldmatrix.sync.aligned.m8n8.x4.trans.shared.b16 {%0,%1,%2,%3}, [%4];"
                         : "=r"(b0), "=r"(b1), "=r"(b2), "=r"(b3) : "r"(b_addr));
            asm volatile("mma.sync.aligned.m16n8k16.row.col.f32.f16.f16.f32 "
                         "{%0,%1,%2,%3}, {%4,%5,%6,%7}, {%8,%9}, {%0,%1,%2,%3};"
                         : "+f"(acc[hn * 2][0]), "+f"(acc[hn * 2][1]),
                           "+f"(acc[hn * 2][2]), "+f"(acc[hn * 2][3])
                         : "r"(a0), "r"(a1), "r"(a2), "r"(a3), "r"(b0), "r"(b1));
            asm volatile("mma.sync.aligned.m16n8k16.row.col.f32.f16.f16.f32 "
                         "{%0,%1,%2,%3}, {%4,%5,%6,%7}, {%8,%9}, {%0,%1,%2,%3};"
                         : "+f"(acc[hn * 2 + 1][0]), "+f"(acc[hn * 2 + 1][1]),
                           "+f"(acc[hn * 2 + 1][2]), "+f"(acc[hn * 2 + 1][3])
                         : "r"(a0), "r"(a1), "r"(a2), "r"(a3), "r"(b2), "r"(b3));
        }
    }

    const float dv0 = ok0 ? rsqrtf(1.0f + (float)__ldg(&g_deg[row0])) : 0.f;
    const float dv1 = ok1 ? rsqrtf(1.0f + (float)__ldg(&g_deg[row1])) : 0.f;
#pragma unroll
    for (int nt = 0; nt < 4; nt++) {
        int c = nb + nt * 8 + cq;
        if (ok0)
            *reinterpret_cast<__half2*>(&g_hp[(size_t)row0 * 64 + c]) =
                __floats2half2_rn(acc[nt][0] * dv0, acc[nt][1] * dv0);
        if (ok1)
            *reinterpret_cast<__half2*>(&g_hp[(size_t)row1 * 64 + c]) =
                __floats2half2_rn(acc[nt][2] * dv1, acc[nt][3] * dv1);
    }
}

// ---------------- fp16 row accumulate helper ----------------
__device__ __forceinline__ void add8(float* acc, float4 v) {
    const __half2* h = reinterpret_cast<const __half2*>(&v);
#pragma unroll
    for (int k = 0; k < 4; k++) {
        float2 f = __half22float2(h[k]);
        acc[2 * k]     += f.x;
        acc[2 * k + 1] += f.y;
    }
}

// ---------------- bucket gather: 8 threads/node, flat predicated 16-window (R12 body) ----------------
// int4 index loads: bucket base (n*48 ints = 192B) is 16B-aligned.
template <int LAYER>
__global__ void __launch_bounds__(256) gather_kernel(const float* __restrict__ b,
                                                     const int* __restrict__ batch) {
    const int tid = threadIdx.x;
    const int q = tid & 7;
    const int nbase = blockIdx.x * 32;
    const int n = nbase + (tid >> 3);             // NN/32 = 3125 exact
    const int c0 = q * 8;

    // per-graph node counts, only needed once (layer 2): warp 0 covers block's 32 nodes
    if (LAYER == 2 && tid < 32) {
        int gr2 = __ldg(&batch[nbase + tid]);
        unsigned mask = __match_any_sync(0xffffffffu, gr2);
        if (tid == __ffs(mask) - 1) atomicAdd(&g_cnt[gr2], (float)__popc(mask));
    }

    float acc[8];
    {   // self term
        float4 v = __ldg(reinterpret_cast<const float4*>(&g_hp[(size_t)n * 64 + c0]));
        const __half2* h = reinterpret_cast<const __half2*>(&v);
#pragma unroll
        for (int k = 0; k < 4; k++) {
            float2 f = __half22float2(h[k]);
            acc[2 * k] = f.x; acc[2 * k + 1] = f.y;
        }
    }

    const int dgr = g_deg[n];                     // broadcast (8 lanes same addr)
    const float dv = rsqrtf(1.0f + (float)dgr);
    const int d = dgr > BK ? BK : dgr;
    const int base = n * BK;

    // flat 16-edge window: vectorized index loads, rows predicated
    int idx[16];
    {
        const int4* cp = reinterpret_cast<const int4*>(&g_col[base]);
#pragma unroll
        for (int k4 = 0; k4 < 4; k4++) {
            int4 iv = __ldg(&cp[k4]);
            idx[k4 * 4 + 0] = iv.x; idx[k4 * 4 + 1] = iv.y;
            idx[k4 * 4 + 2] = iv.z; idx[k4 * 4 + 3] = iv.w;
        }
    }
#pragma unroll
    for (int k = 0; k < 16; k++) {
        float4 v = make_float4(0.f, 0.f, 0.f, 0.f);
        if (k < d)
            v = __ldg(reinterpret_cast<const float4*>(&g_hp[(size_t)idx[k] * 64 + c0]));
        add8(acc, v);
    }
    // rare remainder (deg > 16, ~2% of nodes)
    for (int i = 16; i < d; i += 4) {
        int s[4];
#pragma unroll
        for (int k = 0; k < 4; k++) s[k] = __ldg(&g_col[base + i + k]);
#pragma unroll
        for (int k = 0; k < 4; k++) {
            float4 v = make_float4(0.f, 0.f, 0.f, 0.f);
            if (i + k < d)
                v = __ldg(reinterpret_cast<const float4*>(&g_hp[(size_t)s[k] * 64 + c0]));
            add8(acc, v);
        }
    }

    float4 bv0 = *reinterpret_cast<const float4*>(&b[c0]);
    float4 bv1 = *reinterpret_cast<const float4*>(&b[c0 + 4]);
    float y[8];
    y[0] = fmaf(acc[0], dv, bv0.x); y[1] = fmaf(acc[1], dv, bv0.y);
    y[2] = fmaf(acc[2], dv, bv0.z); y[3] = fmaf(acc[3], dv, bv0.w);
    y[4] = fmaf(acc[4], dv, bv1.x); y[5] = fmaf(acc[5], dv, bv1.y);
    y[6] = fmaf(acc[6], dv, bv1.z); y[7] = fmaf(acc[7], dv, bv1.w);

    if (LAYER < 2) {
        union { uint4 u; __half2 h[4]; } pk;
#pragma unroll
        for (int k = 0; k < 4; k++) pk.h[k] = __floats2half2_rn(y[2 * k], y[2 * k + 1]);
        *reinterpret_cast<uint4*>(&g_buf2h[(size_t)n * 64 + c0]) = pk.u;
    } else {
        // fused mean-pool accumulation (BN3 applied in head); zero deg for next call
        int gr = __ldg(&batch[n]);
        float* p = &g_pooled[(size_t)gr * 64 + c0];
        asm volatile("red.global.add.v4.f32 [%0], {%1,%2,%3,%4};"
                     :: "l"(p), "f"(y[0]), "f"(y[1]), "f"(y[2]), "f"(y[3]) : "memory");
        asm volatile("red.global.add.v4.f32 [%0], {%1,%2,%3,%4};"
                     :: "l"(p + 4), "f"(y[4]), "f"(y[5]), "f"(y[6]), "f"(y[7]) : "memory");
        if (q == 0) g_deg[n] = 0;      // warp-synchronous: all lanes already read deg
    }

    float s[8], s2[8];
#pragma unroll
    for (int k = 0; k < 8; k++) { s[k] = y[k]; s2[k] = y[k] * y[k]; }
#pragma unroll
    for (int k = 0; k < 8; k++) {
        s[k]  += __shfl_xor_sync(0xffffffffu, s[k], 8);
        s2[k] += __shfl_xor_sync(0xffffffffu, s2[k], 8);
        s[k]  += __shfl_xor_sync(0xffffffffu, s[k], 16);
        s2[k] += __shfl_xor_sync(0xffffffffu, s2[k], 16);
    }
    __shared__ float ss[8][64];
    __shared__ float sg[8][64];
    int w = tid >> 5, lane = tid & 31;
    if (lane < 8) {
        *reinterpret_cast<float4*>(&ss[w][c0])     = make_float4(s[0], s[1], s[2], s[3]);
        *reinterpret_cast<float4*>(&ss[w][c0 + 4]) = make_float4(s[4], s[5], s[6], s[7]);
        *reinterpret_cast<float4*>(&sg[w][c0])     = make_float4(s2[0], s2[1], s2[2], s2[3]);
        *reinterpret_cast<float4*>(&sg[w][c0 + 4]) = make_float4(s2[4], s2[5], s2[6], s2[7]);
    }
    __syncthreads();
    if (tid < 64) {
        float a = 0.f, a2 = 0.f;
#pragma unroll
        for (int ww = 0; ww < 8; ww++) { a += ss[ww][tid]; a2 += sg[ww][tid]; }
        atomicAdd(&g_sum[LAYER * HH + tid], a);
        atomicAdd(&g_sq[LAYER * HH + tid], a2);
    }
}

// ---------------- head: BN3 on pooled means, MLP, softmax; zero globals for next call ----------------
__global__ void head_kernel(const float* __restrict__ gm, const float* __restrict__ be,
                            const float* __restrict__ Wl1, const float* __restrict__ bl1,
                            const float* __restrict__ Wl2, const float* __restrict__ bl2,
                            float* __restrict__ out) {
    __shared__ float ps[GG][64];
    __shared__ float zs[GG][33];
    __shared__ float lg[GG][3];
    __shared__ float s_scale[64], s_shift[64];
    int tid = threadIdx.x;   // 256

    if (tid < 64) {
        float invN = 1.0f / (float)NN;
        float m = g_sum[2 * HH + tid] * invN;
        float v = g_sq[2 * HH + tid] * invN - m * m;
        float sc = gm[tid] * rsqrtf(v + 1e-5f);
        s_scale[tid] = sc;
        s_shift[tid] = be[tid] - m * sc;
    }
    __syncthreads();

    for (int i = tid; i < GG * 64; i += 256) {
        int g = i >> 6, c = i & 63;
        float mean = g_pooled[i] / fmaxf(g_cnt[g], 1.0f);
        ps[g][c] = fmaf(mean, s_scale[c], s_shift[c]);
    }
    __syncthreads();

    // zero accumulators for the next call (all dead now)
    for (int i = tid; i < GG * HH; i += 256) g_pooled[i] = 0.0f;
    if (tid < 3 * HH) { g_sum[tid] = 0.0f; g_sq[tid] = 0.0f; }
    if (tid < GG) g_cnt[tid] = 0.0f;

    for (int i = tid; i < GG * 32; i += 256) {
        int g = i >> 5, j = i & 31;
        float acc = bl1[j];
#pragma unroll
        for (int k = 0; k < 64; k++) acc += ps[g][k] * Wl1[k * 32 + j];
        zs[g][j] = fmaxf(acc, 0.0f);
    }
    __syncthreads();
    if (tid < GG * CC) {
        int g = tid / CC, c = tid % CC;
        float acc = bl2[c];
#pragma unroll
        for (int k = 0; k < 32; k++) acc += zs[g][k] * Wl2[k * CC + c];
        lg[g][c] = acc;
    }
    __syncthreads();
    if (tid < GG) {
        float a = lg[tid][0], b = lg[tid][1], c = lg[tid][2];
        float mx = fmaxf(a, fmaxf(b, c));
        float e0 = expf(a - mx), e1 = expf(b - mx), e2 = expf(c - mx);
        float inv = 1.0f / (e0 + e1 + e2);
        out[tid * 3 + 0] = e0 * inv;
        out[tid * 3 + 1] = e1 * inv;
        out[tid * 3 + 2] = e2 * inv;
    }
}

// ---------------- launch ----------------
extern "C" void kernel_launch(void* const* d_in, const int* in_sizes, int n_in,
                              void* d_out, int out_size) {
    const float* x     = (const float*)d_in[0];
    const int*   ei    = (const int*)d_in[1];
    const int*   batch = (const int*)d_in[2];
    const float* W1  = (const float*)d_in[3];
    const float* b1  = (const float*)d_in[4];
    const float* g1  = (const float*)d_in[5];
    const float* be1 = (const float*)d_in[6];
    const float* W2  = (const float*)d_in[7];
    const float* b2  = (const float*)d_in[8];
    const float* g2  = (const float*)d_in[9];
    const float* be2 = (const float*)d_in[10];
    const float* W3  = (const float*)d_in[11];
    const float* b3  = (const float*)d_in[12];
    const float* g3  = (const float*)d_in[13];
    const float* be3 = (const float*)d_in[14];
    const float* Wl1 = (const float*)d_in[15];
    const float* bl1 = (const float*)d_in[16];
    const float* Wl2 = (const float*)d_in[17];
    const float* bl2 = (const float*)d_in[18];
    float* out = (float*)d_out;

    const int GEMM_GRID   = (NN + 63) / 64;           // 1563
    const int GATHER_GRID = NN / 32;                  // 3125
    const int E4_GRID     = (EE / 4 + 255) / 256;     // 977

    __half* w1h; cudaGetSymbolAddress((void**)&w1h, g_w1h);
    __half* w2h; cudaGetSymbolAddress((void**)&w2h, g_w2h);
    __half* w3h; cudaGetSymbolAddress((void**)&w3h, g_w3h);

    prep_kernel<<<16, 256>>>(W1, W2, W3);
    fill_kernel<<<E4_GRID, 256>>>(ei);

    // ---- layer 1 ----
    gemm_kernel<FIN1, 0><<<GEMM_GRID, 256>>>(x, w1h, nullptr, nullptr);
    gather_kernel<0><<<GATHER_GRID, 256>>>(b1, batch);

    // ---- layer 2 ----
    gemm_kernel<HH, 1><<<GEMM_GRID, 256>>>(nullptr, w2h, g1, be1);
    gather_kernel<1><<<GATHER_GRID, 256>>>(b2, batch);

    // ---- layer 3 (gather pools directly) ----
    gemm_kernel<HH, 2><<<GEMM_GRID, 256>>>(nullptr, w3h, g2, be2);
    gather_kernel<2><<<GATHER_GRID, 256>>>(b3, batch);

    // ---- head ----
    head_kernel<<<1, 256>>>(g3, be3, Wl1, bl1, Wl2, bl2, out);
}

// round 15
// speedup vs baseline: 1.1208x; 1.0915x over previous
#include <cuda_runtime.h>
#include <cuda_fp16.h>
#include <cuda_bf16.h>
#include <cstdint>

#define NN 100000
#define EE 1000000
#define HH 64
#define GG 64
#define CC 3
#define FIN1 32
#define BK 48                     // bucket capacity per node (P(deg>48) ~ 1e-16)

// ---------------- scratch ----------------
__device__ __align__(16) __half g_hp[NN * HH];     // h' = (in@W)*dinv, fp16 rows (128B)
__device__ __align__(16) __half g_buf2h[NN * HH];  // y (layers 1,2), fp16
__device__ float g_cnt[GG];
__device__ __align__(16) float g_pooled[GG * HH];
__device__ float g_sum[3 * HH];
__device__ float g_sq[3 * HH];
// fp16 weights (preconverted once per call)
__device__ __align__(16) __half g_w1h[FIN1 * HH];
__device__ __align__(16) __half g_w2h[HH * HH];
__device__ __align__(16) __half g_w3h[HH * HH];
// bucketed CSR
__device__ int g_deg[NN];                          // zeroed by gather<2> each call
__device__ __align__(16) int g_col[NN * BK + 8];

__device__ __forceinline__ uint32_t smem_u32(const void* p) {
    return (uint32_t)__cvta_generic_to_shared(p);
}
__device__ __forceinline__ uint32_t h2u(__half2 h) {
    return *reinterpret_cast<uint32_t*>(&h);
}

// ---------------- prep: convert W1/W2/W3 to fp16 ----------------
__global__ void prep_kernel(const float* __restrict__ W1, const float* __restrict__ W2,
                            const float* __restrict__ W3) {
    int t = blockIdx.x * 256 + threadIdx.x;
    if (t < FIN1 * HH) g_w1h[t] = __float2half(W1[t]);
    if (t < HH * HH) {
        g_w2h[t] = __float2half(W2[t]);
        g_w3h[t] = __float2half(W3[t]);
    }
}

// ---------------- bucket fill: deg count + col scatter in ONE pass ----------------
__global__ void fill_kernel(const int* __restrict__ ei) {
    int e4 = blockIdx.x * blockDim.x + threadIdx.x;
    if (e4 < EE / 4) {
        int4 s = __ldg(reinterpret_cast<const int4*>(ei) + e4);
        int4 d = __ldg(reinterpret_cast<const int4*>(ei + EE) + e4);
        int p;
        p = atomicAdd(&g_deg[d.x], 1); if (p < BK) g_col[d.x * BK + p] = s.x;
        p = atomicAdd(&g_deg[d.y], 1); if (p < BK) g_col[d.y * BK + p] = s.y;
        p = atomicAdd(&g_deg[d.z], 1); if (p < BK) g_col[d.z * BK + p] = s.z;
        p = atomicAdd(&g_deg[d.w], 1); if (p < BK) g_col[d.w * BK + p] = s.w;
    }
}

// ---------------- GEMM via tensor cores: direct-to-fragment A loads ----------------
// 64-node tile; 8 warps: warp w -> rows (w&3)*16.., cols (w>>2)*32..
template <int FIN, int LAYER>
__global__ void __launch_bounds__(256) gemm_kernel(const float* __restrict__ xin,
                                                   const __half* __restrict__ Wh,
                                                   const float* __restrict__ gm,
                                                   const float* __restrict__ be) {
    constexpr int BS = HH + 8;
    __shared__ __half ws[FIN * BS];
    __shared__ float s_scale[64], s_shift[64];

    const int tid = threadIdx.x;
    const int nbase = blockIdx.x * 64;

    if (LAYER > 0 && tid < 64) {
        float invN = 1.0f / (float)NN;
        float m = g_sum[(LAYER - 1) * HH + tid] * invN;
        float v = g_sq[(LAYER - 1) * HH + tid] * invN - m * m;
        float sc = gm[tid] * rsqrtf(v + 1e-5f);
        s_scale[tid] = sc;
        s_shift[tid] = be[tid] - m * sc;
    }
    {   // W staging: fp16, vectorized half2
        const __half2* wsrc = reinterpret_cast<const __half2*>(Wh);
        for (int i = tid; i < FIN * HH / 2; i += 256) {
            int row = i >> 5, col = (i & 31) * 2;
            *reinterpret_cast<__half2*>(&ws[row * BS + col]) = wsrc[i];
        }
    }
    __syncthreads();

    const int w = tid >> 5, lane = tid & 31;
    const int mw = (w & 3) * 16;
    const int nb = (w >> 2) * 32;
    const int cq = (lane & 3) * 2;
    const int row0 = nbase + mw + (lane >> 2);
    const int row1 = row0 + 8;
    const bool ok0 = row0 < NN, ok1 = row1 < NN;

    float acc[4][4] = {{0,0,0,0},{0,0,0,0},{0,0,0,0},{0,0,0,0}};
    const uint32_t ws_base = smem_u32(ws);

#pragma unroll
    for (int k0 = 0; k0 < FIN; k0 += 16) {
        uint32_t a0, a1, a2, a3;
        const int cA = k0 + cq, cB = k0 + cq + 8;
        if (LAYER == 0) {
            float2 z = make_float2(0.f, 0.f);
            float2 f00 = ok0 ? __ldg(reinterpret_cast<const float2*>(&xin[(size_t)row0 * FIN + cA])) : z;
            float2 f10 = ok1 ? __ldg(reinterpret_cast<const float2*>(&xin[(size_t)row1 * FIN + cA])) : z;
            float2 f01 = ok0 ? __ldg(reinterpret_cast<const float2*>(&xin[(size_t)row0 * FIN + cB])) : z;
            float2 f11 = ok1 ? __ldg(reinterpret_cast<const float2*>(&xin[(size_t)row1 * FIN + cB])) : z;
            a0 = h2u(__floats2half2_rn(f00.x, f00.y));
            a1 = h2u(__floats2half2_rn(f10.x, f10.y));
            a2 = h2u(__floats2half2_rn(f01.x, f01.y));
            a3 = h2u(__floats2half2_rn(f11.x, f11.y));
        } else {
            __half2 hz = __floats2half2_rn(0.f, 0.f);
            __half2 h00 = ok0 ? __ldg(reinterpret_cast<const __half2*>(&g_buf2h[(size_t)row0 * 64 + cA])) : hz;
            __half2 h10 = ok1 ? __ldg(reinterpret_cast<const __half2*>(&g_buf2h[(size_t)row1 * 64 + cA])) : hz;
            __half2 h01 = ok0 ? __ldg(reinterpret_cast<const __half2*>(&g_buf2h[(size_t)row0 * 64 + cB])) : hz;
            __half2 h11 = ok1 ? __ldg(reinterpret_cast<const __half2*>(&g_buf2h[(size_t)row1 * 64 + cB])) : hz;
            float sA0 = s_scale[cA], sA1 = s_scale[cA + 1];
            float tA0 = s_shift[cA], tA1 = s_shift[cA + 1];
            float sB0 = s_scale[cB], sB1 = s_scale[cB + 1];
            float tB0 = s_shift[cB], tB1 = s_shift[cB + 1];
            float2 f;
            f = __half22float2(h00);
            a0 = h2u(__floats2half2_rn(fmaxf(fmaf(f.x, sA0, tA0), 0.f), fmaxf(fmaf(f.y, sA1, tA1), 0.f)));
            f = __half22float2(h10);
            a1 = h2u(__floats2half2_rn(fmaxf(fmaf(f.x, sA0, tA0), 0.f), fmaxf(fmaf(f.y, sA1, tA1), 0.f)));
            f = __half22float2(h01);
            a2 = h2u(__floats2half2_rn(fmaxf(fmaf(f.x, sB0, tB0), 0.f), fmaxf(fmaf(f.y, sB1, tB1), 0.f)));
            f = __half22float2(h11);
            a3 = h2u(__floats2half2_rn(fmaxf(fmaf(f.x, sB0, tB0), 0.f), fmaxf(fmaf(f.y, sB1, tB1), 0.f)));
        }
#pragma unroll
        for (int hn = 0; hn < 2; hn++) {
            uint32_t b0, b1, b2, b3;
            uint32_t b_addr = ws_base + ((k0 + (lane & 15)) * BS + nb + hn * 16 + ((lane >> 4) * 8)) * 2;
            asm volatile("ldmatrix.sync.aligned.m8n8.x4.trans.shared.b16 {%0,%1,%2,%3}, [%4];"
                         : "=r"(b0), "=r"(b1), "=r"(b2), "=r"(b3) : "r"(b_addr));
            asm volatile("mma.sync.aligned.m16n8k16.row.col.f32.f16.f16.f32 "
                         "{%0,%1,%2,%3}, {%4,%5,%6,%7}, {%8,%9}, {%0,%1,%2,%3};"
                         : "+f"(acc[hn * 2][0]), "+f"(acc[hn * 2][1]),
                           "+f"(acc[hn * 2][2]), "+f"(acc[hn * 2][3])
                         : "r"(a0), "r"(a1), "r"(a2), "r"(a3), "r"(b0), "r"(b1));
            asm volatile("mma.sync.aligned.m16n8k16.row.col.f32.f16.f16.f32 "
                         "{%0,%1,%2,%3}, {%4,%5,%6,%7}, {%8,%9}, {%0,%1,%2,%3};"
                         : "+f"(acc[hn * 2 + 1][0]), "+f"(acc[hn * 2 + 1][1]),
                           "+f"(acc[hn * 2 + 1][2]), "+f"(acc[hn * 2 + 1][3])
                         : "r"(a0), "r"(a1), "r"(a2), "r"(a3), "r"(b2), "r"(b3));
        }
    }

    const float dv0 = ok0 ? rsqrtf(1.0f + (float)__ldg(&g_deg[row0])) : 0.f;
    const float dv1 = ok1 ? rsqrtf(1.0f + (float)__ldg(&g_deg[row1])) : 0.f;
#pragma unroll
    for (int nt = 0; nt < 4; nt++) {
        int c = nb + nt * 8 + cq;
        if (ok0)
            *reinterpret_cast<__half2*>(&g_hp[(size_t)row0 * 64 + c]) =
                __floats2half2_rn(acc[nt][0] * dv0, acc[nt][1] * dv0);
        if (ok1)
            *reinterpret_cast<__half2*>(&g_hp[(size_t)row1 * 64 + c]) =
                __floats2half2_rn(acc[nt][2] * dv1, acc[nt][3] * dv1);
    }
}

// ---------------- fp16 row accumulate helper ----------------
__device__ __forceinline__ void add8(float* acc, float4 v) {
    const __half2* h = reinterpret_cast<const __half2*>(&v);
#pragma unroll
    for (int k = 0; k < 4; k++) {
        float2 f = __half22float2(h[k]);
        acc[2 * k]     += f.x;
        acc[2 * k + 1] += f.y;
    }
}

// ---------------- bucket gather: 8 threads/node, flat predicated 16-window (R12 body) ----------------
// __launch_bounds__(256, 8): pin the 32-reg / 8-CTA-per-SM occupancy point.
template <int LAYER>
__global__ void __launch_bounds__(256, 8) gather_kernel(const float* __restrict__ b,
                                                        const int* __restrict__ batch) {
    const int tid = threadIdx.x;
    const int q = tid & 7;
    const int nbase = blockIdx.x * 32;
    const int n = nbase + (tid >> 3);             // NN/32 = 3125 exact
    const int c0 = q * 8;

    // per-graph node counts, only needed once (layer 2): warp 0 covers block's 32 nodes
    if (LAYER == 2 && tid < 32) {
        int gr2 = __ldg(&batch[nbase + tid]);
        unsigned mask = __match_any_sync(0xffffffffu, gr2);
        if (tid == __ffs(mask) - 1) atomicAdd(&g_cnt[gr2], (float)__popc(mask));
    }

    float acc[8];
    {   // self term
        float4 v = __ldg(reinterpret_cast<const float4*>(&g_hp[(size_t)n * 64 + c0]));
        const __half2* h = reinterpret_cast<const __half2*>(&v);
#pragma unroll
        for (int k = 0; k < 4; k++) {
            float2 f = __half22float2(h[k]);
            acc[2 * k] = f.x; acc[2 * k + 1] = f.y;
        }
    }

    const int dgr = g_deg[n];                     // broadcast (8 lanes same addr)
    const float dv = rsqrtf(1.0f + (float)dgr);
    const int d = dgr > BK ? BK : dgr;
    const int base = n * BK;

    // flat 16-edge window: indices unconditional, rows predicated
    int idx[16];
#pragma unroll
    for (int k = 0; k < 16; k++) idx[k] = __ldg(&g_col[base + k]);
#pragma unroll
    for (int k = 0; k < 16; k++) {
        float4 v = make_float4(0.f, 0.f, 0.f, 0.f);
        if (k < d)
            v = __ldg(reinterpret_cast<const float4*>(&g_hp[(size_t)idx[k] * 64 + c0]));
        add8(acc, v);
    }
    // rare remainder (deg > 16, ~2% of nodes)
    for (int i = 16; i < d; i += 4) {
        int s[4];
#pragma unroll
        for (int k = 0; k < 4; k++) s[k] = __ldg(&g_col[base + i + k]);
#pragma unroll
        for (int k = 0; k < 4; k++) {
            float4 v = make_float4(0.f, 0.f, 0.f, 0.f);
            if (i + k < d)
                v = __ldg(reinterpret_cast<const float4*>(&g_hp[(size_t)s[k] * 64 + c0]));
            add8(acc, v);
        }
    }

    float4 bv0 = *reinterpret_cast<const float4*>(&b[c0]);
    float4 bv1 = *reinterpret_cast<const float4*>(&b[c0 + 4]);
    float y[8];
    y[0] = fmaf(acc[0], dv, bv0.x); y[1] = fmaf(acc[1], dv, bv0.y);
    y[2] = fmaf(acc[2], dv, bv0.z); y[3] = fmaf(acc[3], dv, bv0.w);
    y[4] = fmaf(acc[4], dv, bv1.x); y[5] = fmaf(acc[5], dv, bv1.y);
    y[6] = fmaf(acc[6], dv, bv1.z); y[7] = fmaf(acc[7], dv, bv1.w);

    if (LAYER < 2) {
        union { uint4 u; __half2 h[4]; } pk;
#pragma unroll
        for (int k = 0; k < 4; k++) pk.h[k] = __floats2half2_rn(y[2 * k], y[2 * k + 1]);
        *reinterpret_cast<uint4*>(&g_buf2h[(size_t)n * 64 + c0]) = pk.u;
    } else {
        // fused mean-pool accumulation (BN3 applied in head); zero deg for next call
        int gr = __ldg(&batch[n]);
        float* p = &g_pooled[(size_t)gr * 64 + c0];
        asm volatile("red.global.add.v4.f32 [%0], {%1,%2,%3,%4};"
                     :: "l"(p), "f"(y[0]), "f"(y[1]), "f"(y[2]), "f"(y[3]) : "memory");
        asm volatile("red.global.add.v4.f32 [%0], {%1,%2,%3,%4};"
                     :: "l"(p + 4), "f"(y[4]), "f"(y[5]), "f"(y[6]), "f"(y[7]) : "memory");
        if (q == 0) g_deg[n] = 0;      // warp-synchronous: all lanes already read deg
    }

    float s[8], s2[8];
#pragma unroll
    for (int k = 0; k < 8; k++) { s[k] = y[k]; s2[k] = y[k] * y[k]; }
#pragma unroll
    for (int k = 0; k < 8; k++) {
        s[k]  += __shfl_xor_sync(0xffffffffu, s[k], 8);
        s2[k] += __shfl_xor_sync(0xffffffffu, s2[k], 8);
        s[k]  += __shfl_xor_sync(0xffffffffu, s[k], 16);
        s2[k] += __shfl_xor_sync(0xffffffffu, s2[k], 16);
    }
    __shared__ float ss[8][64];
    __shared__ float sg[8][64];
    int w = tid >> 5, lane = tid & 31;
    if (lane < 8) {
        *reinterpret_cast<float4*>(&ss[w][c0])     = make_float4(s[0], s[1], s[2], s[3]);
        *reinterpret_cast<float4*>(&ss[w][c0 + 4]) = make_float4(s[4], s[5], s[6], s[7]);
        *reinterpret_cast<float4*>(&sg[w][c0])     = make_float4(s2[0], s2[1], s2[2], s2[3]);
        *reinterpret_cast<float4*>(&sg[w][c0 + 4]) = make_float4(s2[4], s2[5], s2[6], s2[7]);
    }
    __syncthreads();
    if (tid < 64) {
        float a = 0.f, a2 = 0.f;
#pragma unroll
        for (int ww = 0; ww < 8; ww++) { a += ss[ww][tid]; a2 += sg[ww][tid]; }
        atomicAdd(&g_sum[LAYER * HH + tid], a);
        atomicAdd(&g_sq[LAYER * HH + tid], a2);
    }
}

// ---------------- head: BN3 on pooled means, MLP, softmax; zero globals for next call ----------------
__global__ void head_kernel(const float* __restrict__ gm, const float* __restrict__ be,
                            const float* __restrict__ Wl1, const float* __restrict__ bl1,
                            const float* __restrict__ Wl2, const float* __restrict__ bl2,
                            float* __restrict__ out) {
    __shared__ float ps[GG][64];
    __shared__ float zs[GG][33];
    __shared__ float lg[GG][3];
    __shared__ float s_scale[64], s_shift[64];
    int tid = threadIdx.x;   // 256

    if (tid < 64) {
        float invN = 1.0f / (float)NN;
        float m = g_sum[2 * HH + tid] * invN;
        float v = g_sq[2 * HH + tid] * invN - m * m;
        float sc = gm[tid] * rsqrtf(v + 1e-5f);
        s_scale[tid] = sc;
        s_shift[tid] = be[tid] - m * sc;
    }
    __syncthreads();

    for (int i = tid; i < GG * 64; i += 256) {
        int g = i >> 6, c = i & 63;
        float mean = g_pooled[i] / fmaxf(g_cnt[g], 1.0f);
        ps[g][c] = fmaf(mean, s_scale[c], s_shift[c]);
    }
    __syncthreads();

    // zero accumulators for the next call (all dead now)
    for (int i = tid; i < GG * HH; i += 256) g_pooled[i] = 0.0f;
    if (tid < 3 * HH) { g_sum[tid] = 0.0f; g_sq[tid] = 0.0f; }
    if (tid < GG) g_cnt[tid] = 0.0f;

    for (int i = tid; i < GG * 32; i += 256) {
        int g = i >> 5, j = i & 31;
        float acc = bl1[j];
#pragma unroll
        for (int k = 0; k < 64; k++) acc += ps[g][k] * Wl1[k * 32 + j];
        zs[g][j] = fmaxf(acc, 0.0f);
    }
    __syncthreads();
    if (tid < GG * CC) {
        int g = tid / CC, c = tid % CC;
        float acc = bl2[c];
#pragma unroll
        for (int k = 0; k < 32; k++) acc += zs[g][k] * Wl2[k * CC + c];
        lg[g][c] = acc;
    }
    __syncthreads();
    if (tid < GG) {
        float a = lg[tid][0], b = lg[tid][1], c = lg[tid][2];
        float mx = fmaxf(a, fmaxf(b, c));
        float e0 = expf(a - mx), e1 = expf(b - mx), e2 = expf(c - mx);
        float inv = 1.0f / (e0 + e1 + e2);
        out[tid * 3 + 0] = e0 * inv;
        out[tid * 3 + 1] = e1 * inv;
        out[tid * 3 + 2] = e2 * inv;
    }
}

// ---------------- launch ----------------
extern "C" void kernel_launch(void* const* d_in, const int* in_sizes, int n_in,
                              void* d_out, int out_size) {
    const float* x     = (const float*)d_in[0];
    const int*   ei    = (const int*)d_in[1];
    const int*   batch = (const int*)d_in[2];
    const float* W1  = (const float*)d_in[3];
    const float* b1  = (const float*)d_in[4];
    const float* g1  = (const float*)d_in[5];
    const float* be1 = (const float*)d_in[6];
    const float* W2  = (const float*)d_in[7];
    const float* b2  = (const float*)d_in[8];
    const float* g2  = (const float*)d_in[9];
    const float* be2 = (const float*)d_in[10];
    const float* W3  = (const float*)d_in[11];
    const float* b3  = (const float*)d_in[12];
    const float* g3  = (const float*)d_in[13];
    const float* be3 = (const float*)d_in[14];
    const float* Wl1 = (const float*)d_in[15];
    const float* bl1 = (const float*)d_in[16];
    const float* Wl2 = (const float*)d_in[17];
    const float* bl2 = (const float*)d_in[18];
    float* out = (float*)d_out;

    const int GEMM_GRID   = (NN + 63) / 64;           // 1563
    const int GATHER_GRID = NN / 32;                  // 3125
    const int E4_GRID     = (EE / 4 + 255) / 256;     // 977

    __half* w1h; cudaGetSymbolAddress((void**)&w1h, g_w1h);
    __half* w2h; cudaGetSymbolAddress((void**)&w2h, g_w2h);
    __half* w3h; cudaGetSymbolAddress((void**)&w3h, g_w3h);

    prep_kernel<<<16, 256>>>(W1, W2, W3);
    fill_kernel<<<E4_GRID, 256>>>(ei);

    // ---- layer 1 ----
    gemm_kernel<FIN1, 0><<<GEMM_GRID, 256>>>(x, w1h, nullptr, nullptr);
    gather_kernel<0><<<GATHER_GRID, 256>>>(b1, batch);

    // ---- layer 2 ----
    gemm_kernel<HH, 1><<<GEMM_GRID, 256>>>(nullptr, w2h, g1, be1);
    gather_kernel<1><<<GATHER_GRID, 256>>>(b2, batch);

    // ---- layer 3 (gather pools directly) ----
    gemm_kernel<HH, 2><<<GEMM_GRID, 256>>>(nullptr, w3h, g2, be2);
    gather_kernel<2><<<GATHER_GRID, 256>>>(b3, batch);

    // ---- head ----
    head_kernel<<<1, 256>>>(g3, be3, Wl1, bl1, Wl2, bl2, out);
}